// round 11
// baseline (speedup 1.0000x reference)
#include <cuda_runtime.h>
#include <cuda_fp16.h>
#include <cstdint>

// ===================== problem constants =====================
static constexpr int H = 4096;        // hidden (K)
static constexpr int V = 32000;       // vocab (N)
static constexpr int M = 4096;        // tokens (8*512)
static constexpr int BM = 128;        // CTA M tile
static constexpr int BN = 128;        // CTA N tile
static constexpr int BK = 64;         // K chunk (128B of fp16 per row = SW128 atom)
static constexpr int NCHUNK = H / BK; // 64  (multiple of STAGES -> buf = ch&3 across tiles)
static constexpr int STAGES = 4;
static constexpr int NTILE_M = M / BM;               // 32 (power of 2)
static constexpr int NTILE_N = V / BN;               // 250
static constexpr int NTILES = NTILE_M * NTILE_N * 2; // 16000
static constexpr int GRID = 148;      // persistent: 1 CTA per SM
static constexpr int NTHREADS = 512;  // 16 warps: 2 (m) x 8 (n), warp tile 64x16
static constexpr int A_BYTES = BM * BK * 2;           // 16 KB
static constexpr int B_BYTES = BN * BK * 2;           // 16 KB
static constexpr int STAGE_BYTES = A_BYTES + B_BYTES; // 32 KB
static constexpr int SMEM_ROWSUM_OFF = STAGES * STAGE_BYTES; // 131072
static constexpr int SMEM_BYTES = SMEM_ROWSUM_OFF + BM * 4;  // +512

// ===================== device scratch =====================
__device__ __align__(16) __half g_xh[M * H];      // 32 MB fp16
__device__ __align__(16) __half g_wh[2][V * H];   // 2 x 262 MB fp16
__device__ float g_sumexp[2 * M];
__device__ float g_tok[2 * M];
__device__ float g_seqsum[16];   // [0..7] policy per-seq, [8..15] ref per-seq
__device__ int   g_seqcnt[8];

// ===================== helpers =====================
#define SWZ(o) ((o) ^ (((o) >> 3) & 0x70))

__device__ __forceinline__ uint32_t smem_to_u32(const void* p) {
    uint32_t a;
    asm("{ .reg .u64 t; cvta.to.shared.u64 t, %1; cvt.u32.u64 %0, t; }" : "=r"(a) : "l"(p));
    return a;
}

#define CP_ASYNC16(dst_u32, src_ptr) \
    asm volatile("cp.async.cg.shared.global [%0], [%1], 16;" \
                 :: "r"(dst_u32), "l"(src_ptr) : "memory")
#define CP_COMMIT() asm volatile("cp.async.commit_group;" ::: "memory")
#define CP_WAIT2()  asm volatile("cp.async.wait_group 2;" ::: "memory")

#define LDSM4(r0, r1, r2, r3, addr) \
    asm volatile("ldmatrix.sync.aligned.m8n8.x4.shared.b16 {%0,%1,%2,%3}, [%4];" \
                 : "=r"(r0), "=r"(r1), "=r"(r2), "=r"(r3) : "r"(addr))

// f16-accumulate HMMA: D(2 regs = 4 halves) = A(4) * B(2) + C(2)
#define MMA16816F16(c, a, b) \
    asm volatile("mma.sync.aligned.m16n8k16.row.col.f16.f16.f16.f16 " \
                 "{%0,%1}, {%2,%3,%4,%5}, {%6,%7}, {%0,%1};" \
                 : "+r"((c)[0]), "+r"((c)[1]) \
                 : "r"((a)[0]), "r"((a)[1]), "r"((a)[2]), "r"((a)[3]), \
                   "r"((b)[0]), "r"((b)[1]))

// ===================== small kernels =====================
__global__ void zero_kernel() {
    int i = blockIdx.x * blockDim.x + threadIdx.x;
    if (i < 2 * M) {
        g_sumexp[i] = 0.0f;
        g_tok[i] = 0.0f;
    }
    if (i < 16) g_seqsum[i] = 0.0f;
    if (i < 8) g_seqcnt[i] = 0;
}

// which: 0 -> g_xh, 1 -> g_wh[0], 2 -> g_wh[1]
__global__ void cvt_kernel(const float4* __restrict__ s, long n4, int which) {
    __half2* d = (which == 0) ? (__half2*)g_xh : (__half2*)g_wh[which - 1];
    long i = blockIdx.x * (long)blockDim.x + threadIdx.x;
    long stride = (long)gridDim.x * blockDim.x;
    for (; i < n4; i += stride) {
        float4 v = s[i];
        d[2 * i]     = __floats2half2_rn(v.x, v.y);
        d[2 * i + 1] = __floats2half2_rn(v.z, v.w);
    }
}

// ===================== persistent GEMM + fused softmax-stats =====================
// grid 148, block 512. Tile id t: m = t & 31, u = t >> 5, z = u >= 250, n = u - z*250
// (m-fastest => 32 consecutive tiles share one B tile => L2 reuse as in grid launch).
// Pointers decoded ONCE per tile; the cp.async ring runs continuously across tile
// boundaries so the next tile's first 3 chunks load under the current tile's tail.
__global__ void __launch_bounds__(NTHREADS, 1) dpo_gemm_kernel(
    const long long* __restrict__ y) {
    extern __shared__ char smem[];
    const uint32_t sbase = smem_to_u32(smem);
    const int tid = threadIdx.x;
    const int wid = tid >> 5, lane = tid & 31;
    const int bid = blockIdx.x;
    const int warp_m = wid & 1;   // 0..1
    const int warp_n = wid >> 1;  // 0..7

    float* s_row = (float*)(smem + SMEM_ROWSUM_OFF);
    if (tid < BM) s_row[tid] = 0.0f;

    const int mytiles = (NTILES - bid + GRID - 1) / GRID;

    auto decode = [&](int tile, const __half*& a, const __half*& b,
                      int& mb, int& vb, int& zz) {
        int mm = tile & (NTILE_M - 1);
        int u = tile >> 5;
        int z = (u >= NTILE_N) ? 1 : 0;
        int nn = u - z * NTILE_N;
        mb = mm * BM; vb = nn * BN; zz = z;
        a = g_xh + (size_t)mb * H;
        b = g_wh[z] + (size_t)vb * H;
    };

    const __half *ag_cur, *bg_cur, *ag_nxt, *bg_nxt;
    int mb_cur, vb_cur, z_cur, mb_nxt, vb_nxt, z_nxt;
    decode(bid, ag_cur, bg_cur, mb_cur, vb_cur, z_cur);
    if (mytiles > 1) decode(bid + GRID, ag_nxt, bg_nxt, mb_nxt, vb_nxt, z_nxt);
    else { ag_nxt = ag_cur; bg_nxt = bg_cur; mb_nxt = mb_cur; vb_nxt = vb_cur; z_nxt = z_cur; }

    // load chunk ch (of the tile whose base pointers are given) into stage ch&3
    auto load_chunk = [&](const __half* ag, const __half* bg, int ch) {
        const uint32_t sa = sbase + (ch & (STAGES - 1)) * STAGE_BYTES;
        const uint32_t sb = sa + A_BYTES;
        const int k0 = ch * BK;
        #pragma unroll
        for (int it = 0; it < 2; ++it) {           // A: 128 rows x 8 granules
            int idx = tid + it * NTHREADS;
            int row = idx >> 3, g = idx & 7;
            CP_ASYNC16(sa + SWZ(row * 128 + g * 16),
                       ag + (size_t)row * H + k0 + g * 8);
        }
        #pragma unroll
        for (int it = 0; it < 2; ++it) {           // B: 128 rows x 8 granules
            int idx = tid + it * NTHREADS;
            int row = idx >> 3, g = idx & 7;
            CP_ASYNC16(sb + SWZ(row * 128 + g * 16),
                       bg + (size_t)row * H + k0 + g * 8);
        }
        CP_COMMIT();
    };

    load_chunk(ag_cur, bg_cur, 0);
    load_chunk(ag_cur, bg_cur, 1);
    load_chunk(ag_cur, bg_cur, 2);

    const int g8 = lane >> 3, r8 = lane & 7;

    for (int lt = 0; lt < mytiles; ++lt) {
        const bool has_next = (lt + 1 < mytiles);

        // fp32 master accumulators: 4 m16 x 2 n8 x 4 = 32 regs
        float c[4][2][4];
        #pragma unroll
        for (int i = 0; i < 4; ++i)
            #pragma unroll
            for (int j = 0; j < 2; ++j)
                #pragma unroll
                for (int k = 0; k < 4; ++k) c[i][j][k] = 0.0f;

        for (int ch = 0; ch < NCHUNK; ++ch) {
            CP_WAIT2();
            __syncthreads();

            const int pf = ch + 3;
            if (pf < NCHUNK)      load_chunk(ag_cur, bg_cur, pf);
            else if (has_next)    load_chunk(ag_nxt, bg_nxt, pf - NCHUNK);
            else                  CP_COMMIT();   // uniform group accounting

            const uint32_t sa = sbase + (ch & (STAGES - 1)) * STAGE_BYTES;
            const uint32_t sb = sa + A_BYTES;

            // f16 chunk accumulators (zeroed each chunk)
            uint32_t hc[4][2][2];
            #pragma unroll
            for (int mi = 0; mi < 4; ++mi)
                #pragma unroll
                for (int ni = 0; ni < 2; ++ni)
                    hc[mi][ni][0] = hc[mi][ni][1] = 0u;

            #pragma unroll
            for (int j = 0; j < 4; ++j) {   // 4 k16 steps per 64-chunk
                uint32_t a[4][4];
                #pragma unroll
                for (int mi = 0; mi < 4; ++mi) {
                    int row = warp_m * 64 + mi * 16 + (g8 & 1) * 8 + r8;
                    int kb = j * 32 + (g8 >> 1) * 16;
                    LDSM4(a[mi][0], a[mi][1], a[mi][2], a[mi][3],
                          sa + SWZ(row * 128 + kb));
                }
                uint32_t b[2][2];
                {
                    int row = warp_n * 16 + (g8 >> 1) * 8 + r8;
                    int kb = j * 32 + (g8 & 1) * 16;
                    LDSM4(b[0][0], b[0][1], b[1][0], b[1][1],
                          sb + SWZ(row * 128 + kb));
                }
                #pragma unroll
                for (int mi = 0; mi < 4; ++mi)
                    #pragma unroll
                    for (int ni = 0; ni < 2; ++ni)
                        MMA16816F16(hc[mi][ni], a[mi], b[ni]);
            }

            // promote f16 chunk partials into fp32 masters
            #pragma unroll
            for (int mi = 0; mi < 4; ++mi)
                #pragma unroll
                for (int ni = 0; ni < 2; ++ni) {
                    float2 lo = __half22float2(*(__half2*)&hc[mi][ni][0]);
                    float2 hi = __half22float2(*(__half2*)&hc[mi][ni][1]);
                    c[mi][ni][0] += lo.x;
                    c[mi][ni][1] += lo.y;
                    c[mi][ni][2] += hi.x;
                    c[mi][ni][3] += hi.y;
                }
        }

        // ---- fused epilogue: Sum(exp(logit)) per row + target-logit gather ----
        // (next tile's chunks 0..2 are streaming in concurrently)
        const int m_base = mb_cur, v_base = vb_cur, z = z_cur;
        const int tgrp = lane >> 2;
        const int tcol = lane & 3;

        #pragma unroll
        for (int mi = 0; mi < 4; ++mi) {
            const int row0 = m_base + warp_m * 64 + mi * 16 + tgrp;
            const int row1 = row0 + 8;
            const int t0 = (int)y[row0] - (v_base + warp_n * 16);
            const int t1 = (int)y[row1] - (v_base + warp_n * 16);

            float s0 = 0.0f, s1 = 0.0f;
            #pragma unroll
            for (int ni = 0; ni < 2; ++ni) {
                s0 += __expf(c[mi][ni][0]) + __expf(c[mi][ni][1]);
                s1 += __expf(c[mi][ni][2]) + __expf(c[mi][ni][3]);
            }
            if (t0 >= 0 && t0 < 16 && ((t0 & 7) >> 1) == tcol)
                g_tok[z * M + row0] = c[mi][t0 >> 3][t0 & 1];
            if (t1 >= 0 && t1 < 16 && ((t1 & 7) >> 1) == tcol)
                g_tok[z * M + row1] = c[mi][t1 >> 3][2 + (t1 & 1)];

            s0 += __shfl_xor_sync(0xFFFFFFFFu, s0, 1);
            s0 += __shfl_xor_sync(0xFFFFFFFFu, s0, 2);
            s1 += __shfl_xor_sync(0xFFFFFFFFu, s1, 1);
            s1 += __shfl_xor_sync(0xFFFFFFFFu, s1, 2);
            if (tcol == 0) {
                atomicAdd(&s_row[warp_m * 64 + mi * 16 + tgrp], s0);
                atomicAdd(&s_row[warp_m * 64 + mi * 16 + tgrp + 8], s1);
            }
        }
        __syncthreads();
        if (tid < BM) {
            atomicAdd(&g_sumexp[z * M + m_base + tid], s_row[tid]);
            s_row[tid] = 0.0f;  // same thread re-zeros: ordered for next tile
        }

        // rotate tile pointers; decode tile lt+2 (once per tile, negligible)
        ag_cur = ag_nxt; bg_cur = bg_nxt;
        mb_cur = mb_nxt; vb_cur = vb_nxt; z_cur = z_nxt;
        if (lt + 2 < mytiles)
            decode(bid + (lt + 2) * GRID, ag_nxt, bg_nxt, mb_nxt, vb_nxt, z_nxt);
    }
}

// ===================== parallel per-token logp reduction =====================
__global__ void logp_kernel(const long long* __restrict__ y) {
    __shared__ float s_sum[16];
    __shared__ int s_cnt[8];
    if (threadIdx.x < 16) s_sum[threadIdx.x] = 0.0f;
    if (threadIdx.x < 8) s_cnt[threadIdx.x] = 0;
    __syncthreads();

    const int t = blockIdx.x * blockDim.x + threadIdx.x;  // 4096 threads = M tokens
    if (t < M) {
        long long yt = y[t];
        if (yt != -100) {
            int seq = t >> 9;  // 512 tokens per sequence
            float p0 = g_tok[t]     - __logf(g_sumexp[t]);
            float p1 = g_tok[M + t] - __logf(g_sumexp[M + t]);
            atomicAdd(&s_sum[seq], p0);
            atomicAdd(&s_sum[8 + seq], p1);
            atomicAdd(&s_cnt[seq], 1);
        }
    }
    __syncthreads();
    if (threadIdx.x < 16 && s_sum[threadIdx.x] != 0.0f)
        atomicAdd(&g_seqsum[threadIdx.x], s_sum[threadIdx.x]);
    if (threadIdx.x < 8 && s_cnt[threadIdx.x] != 0)
        atomicAdd(&g_seqcnt[threadIdx.x], s_cnt[threadIdx.x]);
}

// ===================== DPO combine (tiny) =====================
__global__ void loss_kernel(float* __restrict__ out) {
    if (threadIdx.x == 0) {
        float loss = 0.0f;
        for (int i = 0; i < 4; ++i) {
            int cc = g_seqcnt[i] > 0 ? g_seqcnt[i] : 1;
            int cr = g_seqcnt[4 + i] > 0 ? g_seqcnt[4 + i] : 1;
            float pc = g_seqsum[i] / cc;
            float pr = g_seqsum[4 + i] / cr;
            float rc = g_seqsum[8 + i] / cc;
            float rr = g_seqsum[12 + i] / cr;
            float zd = 0.1f * ((pc - rc) - (pr - rr));
            loss += (zd > 0.0f) ? log1pf(expf(-zd)) : (-zd + log1pf(expf(zd)));
        }
        out[0] = loss * 0.25f;
    }
}

// ===================== launcher =====================
extern "C" void kernel_launch(void* const* d_in, const int* in_sizes, int n_in,
                              void* d_out, int out_size) {
    const float* x     = (const float*)d_in[0];
    const long long* y = (const long long*)d_in[1];
    const float* Wm    = (const float*)d_in[2];
    const float* rWm   = (const float*)d_in[3];
    float* out         = (float*)d_out;

    cudaFuncSetAttribute(dpo_gemm_kernel,
                         cudaFuncAttributeMaxDynamicSharedMemorySize, SMEM_BYTES);

    zero_kernel<<<32, 256>>>();
    cvt_kernel<<<2048, 256>>>((const float4*)x,   (long)M * H / 4, 0);
    cvt_kernel<<<8192, 256>>>((const float4*)Wm,  (long)V * H / 4, 1);
    cvt_kernel<<<8192, 256>>>((const float4*)rWm, (long)V * H / 4, 2);

    dpo_gemm_kernel<<<GRID, NTHREADS, SMEM_BYTES>>>(y);

    logp_kernel<<<16, 256>>>(y);
    loss_kernel<<<1, 32>>>(out);
}

// round 12
// speedup vs baseline: 1.1663x; 1.1663x over previous
#include <cuda_runtime.h>
#include <cuda_fp16.h>
#include <cstdint>

// ===================== problem constants =====================
static constexpr int H = 4096;        // hidden (K)
static constexpr int V = 32000;       // vocab (N)
static constexpr int M = 4096;        // tokens (8*512)
static constexpr int BM = 128;        // CTA M tile
static constexpr int BN = 64;         // CTA N tile (halved -> 2 CTAs/SM co-resident)
static constexpr int BK = 64;         // K chunk (128B of fp16 per row = SW128 atom)
static constexpr int NCHUNK = H / BK; // 64
static constexpr int STAGES = 4;
static constexpr int NTHREADS = 256;  // 8 warps: 2 (m) x 4 (n), warp tile 64x16
static constexpr int A_BYTES = BM * BK * 2;           // 16 KB
static constexpr int B_BYTES = BN * BK * 2;           // 8 KB
static constexpr int STAGE_BYTES = A_BYTES + B_BYTES; // 24 KB
static constexpr int SMEM_ROWSUM_OFF = STAGES * STAGE_BYTES; // 98304
static constexpr int SMEM_BYTES = SMEM_ROWSUM_OFF + BM * 4;  // 98816 (x2 = 197632 < 228KB)

// ===================== device scratch =====================
__device__ __align__(16) __half g_xh[M * H];      // 32 MB fp16
__device__ __align__(16) __half g_wh[2][V * H];   // 2 x 262 MB fp16
__device__ float g_sumexp[2 * M];
__device__ float g_tok[2 * M];
__device__ float g_seqsum[16];   // [0..7] policy per-seq, [8..15] ref per-seq
__device__ int   g_seqcnt[8];

// ===================== helpers =====================
#define SWZ(o) ((o) ^ (((o) >> 3) & 0x70))

__device__ __forceinline__ uint32_t smem_to_u32(const void* p) {
    uint32_t a;
    asm("{ .reg .u64 t; cvta.to.shared.u64 t, %1; cvt.u32.u64 %0, t; }" : "=r"(a) : "l"(p));
    return a;
}

#define CP_ASYNC16(dst_u32, src_ptr) \
    asm volatile("cp.async.cg.shared.global [%0], [%1], 16;" \
                 :: "r"(dst_u32), "l"(src_ptr) : "memory")
#define CP_COMMIT() asm volatile("cp.async.commit_group;" ::: "memory")
#define CP_WAIT2()  asm volatile("cp.async.wait_group 2;" ::: "memory")

#define LDSM4(r0, r1, r2, r3, addr) \
    asm volatile("ldmatrix.sync.aligned.m8n8.x4.shared.b16 {%0,%1,%2,%3}, [%4];" \
                 : "=r"(r0), "=r"(r1), "=r"(r2), "=r"(r3) : "r"(addr))

// f16-accumulate HMMA: D(2 regs = 4 halves) = A(4) * B(2) + C(2)
#define MMA16816F16(c, a, b) \
    asm volatile("mma.sync.aligned.m16n8k16.row.col.f16.f16.f16.f16 " \
                 "{%0,%1}, {%2,%3,%4,%5}, {%6,%7}, {%0,%1};" \
                 : "+r"((c)[0]), "+r"((c)[1]) \
                 : "r"((a)[0]), "r"((a)[1]), "r"((a)[2]), "r"((a)[3]), \
                   "r"((b)[0]), "r"((b)[1]))

// ===================== small kernels =====================
__global__ void zero_kernel() {
    int i = blockIdx.x * blockDim.x + threadIdx.x;
    if (i < 2 * M) {
        g_sumexp[i] = 0.0f;
        g_tok[i] = 0.0f;
    }
    if (i < 16) g_seqsum[i] = 0.0f;
    if (i < 8) g_seqcnt[i] = 0;
}

// which: 0 -> g_xh, 1 -> g_wh[0], 2 -> g_wh[1]
__global__ void cvt_kernel(const float4* __restrict__ s, long n4, int which) {
    __half2* d = (which == 0) ? (__half2*)g_xh : (__half2*)g_wh[which - 1];
    long i = blockIdx.x * (long)blockDim.x + threadIdx.x;
    long stride = (long)gridDim.x * blockDim.x;
    for (; i < n4; i += stride) {
        float4 v = s[i];
        d[2 * i]     = __floats2half2_rn(v.x, v.y);
        d[2 * i + 1] = __floats2half2_rn(v.z, v.w);
    }
}

// ===================== main GEMM + fused softmax-stats kernel =====================
// grid (M/BM=32, V/BN=500, 2), block 256 (8 warps: 2 m x 4 n, warp tile 64x16)
// 2 CTAs co-resident per SM: one CTA's prologue fill + epilogue hide under the
// other CTA's mainloop; combined 4 MMA warps/SMSP keeps the f16-acc pipe saturated.
__global__ void __launch_bounds__(NTHREADS, 2) dpo_gemm_kernel(
    const long long* __restrict__ y) {
    extern __shared__ char smem[];
    const uint32_t sbase = smem_to_u32(smem);
    const int tid = threadIdx.x;
    const int wid = tid >> 5, lane = tid & 31;
    const int m_base = blockIdx.x * BM;
    const int v_base = blockIdx.y * BN;
    const int z = blockIdx.z;
    const int warp_m = wid & 1;   // 0..1
    const int warp_n = wid >> 1;  // 0..3

    float* s_row = (float*)(smem + SMEM_ROWSUM_OFF);
    if (tid < BM) s_row[tid] = 0.0f;

    const __half* __restrict__ ag = g_xh + (size_t)m_base * H;
    const __half* __restrict__ bg = g_wh[z] + (size_t)v_base * H;

    // fp32 master accumulators: 4 m16 x 2 n8 x 4 = 32 regs
    float c[4][2][4];
    #pragma unroll
    for (int i = 0; i < 4; ++i)
        #pragma unroll
        for (int j = 0; j < 2; ++j)
            #pragma unroll
            for (int k = 0; k < 4; ++k) c[i][j][k] = 0.0f;

    auto load_chunk = [&](int ch) {
        const int buf = ch & (STAGES - 1);
        const uint32_t sa = sbase + buf * STAGE_BYTES;
        const uint32_t sb = sa + A_BYTES;
        const int k0 = ch * BK;
        #pragma unroll
        for (int it = 0; it < 4; ++it) {           // A: 128 rows x 8 granules
            int idx = tid + it * NTHREADS;
            int row = idx >> 3, g = idx & 7;
            CP_ASYNC16(sa + SWZ(row * 128 + g * 16),
                       ag + (size_t)row * H + k0 + g * 8);
        }
        #pragma unroll
        for (int it = 0; it < 2; ++it) {           // B: 64 rows x 8 granules
            int idx = tid + it * NTHREADS;
            int row = idx >> 3, g = idx & 7;
            CP_ASYNC16(sb + SWZ(row * 128 + g * 16),
                       bg + (size_t)row * H + k0 + g * 8);
        }
        CP_COMMIT();
    };

    load_chunk(0);
    load_chunk(1);
    load_chunk(2);

    const int g8 = lane >> 3, r8 = lane & 7;

    for (int ch = 0; ch < NCHUNK; ++ch) {
        CP_WAIT2();
        __syncthreads();
        if (ch + 3 < NCHUNK) load_chunk(ch + 3);
        else CP_COMMIT();

        const int buf = ch & (STAGES - 1);
        const uint32_t sa = sbase + buf * STAGE_BYTES;
        const uint32_t sb = sa + A_BYTES;

        // f16 chunk accumulators (zeroed each chunk): 4 m x 2 n x 2 regs = 16
        uint32_t hc[4][2][2];
        #pragma unroll
        for (int mi = 0; mi < 4; ++mi)
            #pragma unroll
            for (int ni = 0; ni < 2; ++ni)
                hc[mi][ni][0] = hc[mi][ni][1] = 0u;

        #pragma unroll
        for (int j = 0; j < 4; ++j) {   // 4 k16 steps per 64-chunk
            uint32_t a[4][4];
            #pragma unroll
            for (int mi = 0; mi < 4; ++mi) {
                int row = warp_m * 64 + mi * 16 + (g8 & 1) * 8 + r8;
                int kb = j * 32 + (g8 >> 1) * 16;
                LDSM4(a[mi][0], a[mi][1], a[mi][2], a[mi][3],
                      sa + SWZ(row * 128 + kb));
            }
            uint32_t b[2][2];
            {
                int row = warp_n * 16 + (g8 >> 1) * 8 + r8;
                int kb = j * 32 + (g8 & 1) * 16;
                LDSM4(b[0][0], b[0][1], b[1][0], b[1][1],
                      sb + SWZ(row * 128 + kb));
            }
            #pragma unroll
            for (int mi = 0; mi < 4; ++mi)
                #pragma unroll
                for (int ni = 0; ni < 2; ++ni)
                    MMA16816F16(hc[mi][ni], a[mi], b[ni]);
        }

        // promote f16 chunk partials into fp32 masters
        #pragma unroll
        for (int mi = 0; mi < 4; ++mi)
            #pragma unroll
            for (int ni = 0; ni < 2; ++ni) {
                float2 lo = __half22float2(*(__half2*)&hc[mi][ni][0]);
                float2 hi = __half22float2(*(__half2*)&hc[mi][ni][1]);
                c[mi][ni][0] += lo.x;
                c[mi][ni][1] += lo.y;
                c[mi][ni][2] += hi.x;
                c[mi][ni][3] += hi.y;
            }
    }

    // ---- fused epilogue: Sum(exp(logit)) per row + target-logit gather ----
    const int tgrp = lane >> 2;   // row-in-8
    const int tcol = lane & 3;    // col pair index

    #pragma unroll
    for (int mi = 0; mi < 4; ++mi) {
        const int row0 = m_base + warp_m * 64 + mi * 16 + tgrp;
        const int row1 = row0 + 8;
        const int t0 = (int)y[row0] - (v_base + warp_n * 16);  // target col in warp tile
        const int t1 = (int)y[row1] - (v_base + warp_n * 16);

        float s0 = 0.0f, s1 = 0.0f;
        #pragma unroll
        for (int ni = 0; ni < 2; ++ni) {
            s0 += __expf(c[mi][ni][0]) + __expf(c[mi][ni][1]);
            s1 += __expf(c[mi][ni][2]) + __expf(c[mi][ni][3]);
        }
        if (t0 >= 0 && t0 < 16 && ((t0 & 7) >> 1) == tcol)
            g_tok[z * M + row0] = c[mi][t0 >> 3][t0 & 1];
        if (t1 >= 0 && t1 < 16 && ((t1 & 7) >> 1) == tcol)
            g_tok[z * M + row1] = c[mi][t1 >> 3][2 + (t1 & 1)];

        s0 += __shfl_xor_sync(0xFFFFFFFFu, s0, 1);
        s0 += __shfl_xor_sync(0xFFFFFFFFu, s0, 2);
        s1 += __shfl_xor_sync(0xFFFFFFFFu, s1, 1);
        s1 += __shfl_xor_sync(0xFFFFFFFFu, s1, 2);
        if (tcol == 0) {
            atomicAdd(&s_row[warp_m * 64 + mi * 16 + tgrp], s0);
            atomicAdd(&s_row[warp_m * 64 + mi * 16 + tgrp + 8], s1);
        }
    }
    __syncthreads();
    if (tid < BM) atomicAdd(&g_sumexp[z * M + m_base + tid], s_row[tid]);
}

// ===================== parallel per-token logp reduction =====================
__global__ void logp_kernel(const long long* __restrict__ y) {
    __shared__ float s_sum[16];
    __shared__ int s_cnt[8];
    if (threadIdx.x < 16) s_sum[threadIdx.x] = 0.0f;
    if (threadIdx.x < 8) s_cnt[threadIdx.x] = 0;
    __syncthreads();

    const int t = blockIdx.x * blockDim.x + threadIdx.x;  // 4096 threads = M tokens
    if (t < M) {
        long long yt = y[t];
        if (yt != -100) {
            int seq = t >> 9;  // 512 tokens per sequence
            float p0 = g_tok[t]     - __logf(g_sumexp[t]);
            float p1 = g_tok[M + t] - __logf(g_sumexp[M + t]);
            atomicAdd(&s_sum[seq], p0);
            atomicAdd(&s_sum[8 + seq], p1);
            atomicAdd(&s_cnt[seq], 1);
        }
    }
    __syncthreads();
    if (threadIdx.x < 16 && s_sum[threadIdx.x] != 0.0f)
        atomicAdd(&g_seqsum[threadIdx.x], s_sum[threadIdx.x]);
    if (threadIdx.x < 8 && s_cnt[threadIdx.x] != 0)
        atomicAdd(&g_seqcnt[threadIdx.x], s_cnt[threadIdx.x]);
}

// ===================== DPO combine (tiny) =====================
__global__ void loss_kernel(float* __restrict__ out) {
    if (threadIdx.x == 0) {
        float loss = 0.0f;
        for (int i = 0; i < 4; ++i) {
            int cc = g_seqcnt[i] > 0 ? g_seqcnt[i] : 1;
            int cr = g_seqcnt[4 + i] > 0 ? g_seqcnt[4 + i] : 1;
            float pc = g_seqsum[i] / cc;
            float pr = g_seqsum[4 + i] / cr;
            float rc = g_seqsum[8 + i] / cc;
            float rr = g_seqsum[12 + i] / cr;
            float zd = 0.1f * ((pc - rc) - (pr - rr));
            loss += (zd > 0.0f) ? log1pf(expf(-zd)) : (-zd + log1pf(expf(zd)));
        }
        out[0] = loss * 0.25f;
    }
}

// ===================== launcher =====================
extern "C" void kernel_launch(void* const* d_in, const int* in_sizes, int n_in,
                              void* d_out, int out_size) {
    const float* x     = (const float*)d_in[0];
    const long long* y = (const long long*)d_in[1];
    const float* Wm    = (const float*)d_in[2];
    const float* rWm   = (const float*)d_in[3];
    float* out         = (float*)d_out;

    cudaFuncSetAttribute(dpo_gemm_kernel,
                         cudaFuncAttributeMaxDynamicSharedMemorySize, SMEM_BYTES);

    zero_kernel<<<32, 256>>>();
    cvt_kernel<<<2048, 256>>>((const float4*)x,   (long)M * H / 4, 0);
    cvt_kernel<<<8192, 256>>>((const float4*)Wm,  (long)V * H / 4, 1);
    cvt_kernel<<<8192, 256>>>((const float4*)rWm, (long)V * H / 4, 2);

    dim3 grid(M / BM, V / BN, 2);
    dpo_gemm_kernel<<<grid, NTHREADS, SMEM_BYTES>>>(y);

    logp_kernel<<<16, 256>>>(y);
    loss_kernel<<<1, 32>>>(out);
}

// round 13
// speedup vs baseline: 1.2500x; 1.0717x over previous
#include <cuda_runtime.h>
#include <cuda_fp16.h>
#include <cstdint>

// ===================== problem constants =====================
static constexpr int H = 4096;        // hidden (K)
static constexpr int V = 32000;       // vocab (N)
static constexpr int M = 4096;        // tokens (8*512)
static constexpr int BM = 128;        // CTA M tile
static constexpr int BN = 64;         // CTA N tile (2 CTAs/SM co-resident)
static constexpr int BK = 64;         // K chunk (128B of fp16 per row = SW128 atom)
static constexpr int NCHUNK = H / BK; // 64 (processed in pairs)
static constexpr int STAGES = 4;
static constexpr int NTHREADS = 256;  // 8 warps: 2 (m) x 4 (n), warp tile 64x16
static constexpr int A_BYTES = BM * BK * 2;           // 16 KB
static constexpr int B_BYTES = BN * BK * 2;           // 8 KB
static constexpr int STAGE_BYTES = A_BYTES + B_BYTES; // 24 KB
static constexpr int SMEM_ROWSUM_OFF = STAGES * STAGE_BYTES; // 98304
static constexpr int SMEM_BYTES = SMEM_ROWSUM_OFF + BM * 4;  // 98816 (x2 < 228KB)

// ===================== device scratch =====================
__device__ __align__(16) __half g_xh[M * H];      // 32 MB fp16
__device__ __align__(16) __half g_wh[2][V * H];   // 2 x 262 MB fp16
__device__ float g_sumexp[2 * M];
__device__ float g_tok[2 * M];
__device__ float g_seqsum[16];   // [0..7] policy per-seq, [8..15] ref per-seq
__device__ int   g_seqcnt[8];

// ===================== helpers =====================
#define SWZ(o) ((o) ^ (((o) >> 3) & 0x70))

__device__ __forceinline__ uint32_t smem_to_u32(const void* p) {
    uint32_t a;
    asm("{ .reg .u64 t; cvta.to.shared.u64 t, %1; cvt.u32.u64 %0, t; }" : "=r"(a) : "l"(p));
    return a;
}

#define CP_ASYNC16(dst_u32, src_ptr) \
    asm volatile("cp.async.cg.shared.global [%0], [%1], 16;" \
                 :: "r"(dst_u32), "l"(src_ptr) : "memory")
#define CP_COMMIT() asm volatile("cp.async.commit_group;" ::: "memory")
#define CP_WAIT0()  asm volatile("cp.async.wait_group 0;" ::: "memory")

#define LDSM4(r0, r1, r2, r3, addr) \
    asm volatile("ldmatrix.sync.aligned.m8n8.x4.shared.b16 {%0,%1,%2,%3}, [%4];" \
                 : "=r"(r0), "=r"(r1), "=r"(r2), "=r"(r3) : "r"(addr))

// f16-accumulate HMMA: D(2 regs = 4 halves) = A(4) * B(2) + C(2)
#define MMA16816F16(c, a, b) \
    asm volatile("mma.sync.aligned.m16n8k16.row.col.f16.f16.f16.f16 " \
                 "{%0,%1}, {%2,%3,%4,%5}, {%6,%7}, {%0,%1};" \
                 : "+r"((c)[0]), "+r"((c)[1]) \
                 : "r"((a)[0]), "r"((a)[1]), "r"((a)[2]), "r"((a)[3]), \
                   "r"((b)[0]), "r"((b)[1]))

// ===================== small kernels =====================
__global__ void zero_kernel() {
    int i = blockIdx.x * blockDim.x + threadIdx.x;
    if (i < 2 * M) {
        g_sumexp[i] = 0.0f;
        g_tok[i] = 0.0f;
    }
    if (i < 16) g_seqsum[i] = 0.0f;
    if (i < 8) g_seqcnt[i] = 0;
}

// which: 0 -> g_xh, 1 -> g_wh[0], 2 -> g_wh[1]
__global__ void cvt_kernel(const float4* __restrict__ s, long n4, int which) {
    __half2* d = (which == 0) ? (__half2*)g_xh : (__half2*)g_wh[which - 1];
    long i = blockIdx.x * (long)blockDim.x + threadIdx.x;
    long stride = (long)gridDim.x * blockDim.x;
    for (; i < n4; i += stride) {
        float4 v = s[i];
        d[2 * i]     = __floats2half2_rn(v.x, v.y);
        d[2 * i + 1] = __floats2half2_rn(v.z, v.w);
    }
}

// ===================== main GEMM + fused softmax-stats kernel =====================
// grid (M/BM=32, V/BN=500, 2), block 256 (8 warps: 2 m x 4 n, warp tile 64x16)
// 2 CTAs co-resident per SM. Chunks processed in PAIRS: one wait_group-0 + one
// __syncthreads + one fp32-promote per 2 chunks (double-double buffering on the
// 4-stage ring: compute bufs {ch,ch+1} while loading bufs {ch+2,ch+3}).
__global__ void __launch_bounds__(NTHREADS, 2) dpo_gemm_kernel(
    const long long* __restrict__ y) {
    extern __shared__ char smem[];
    const uint32_t sbase = smem_to_u32(smem);
    const int tid = threadIdx.x;
    const int wid = tid >> 5, lane = tid & 31;
    const int m_base = blockIdx.x * BM;
    const int v_base = blockIdx.y * BN;
    const int z = blockIdx.z;
    const int warp_m = wid & 1;   // 0..1
    const int warp_n = wid >> 1;  // 0..3

    float* s_row = (float*)(smem + SMEM_ROWSUM_OFF);
    if (tid < BM) s_row[tid] = 0.0f;

    const __half* __restrict__ ag = g_xh + (size_t)m_base * H;
    const __half* __restrict__ bg = g_wh[z] + (size_t)v_base * H;

    // fp32 master accumulators: 4 m16 x 2 n8 x 4 = 32 regs
    float c[4][2][4];
    #pragma unroll
    for (int i = 0; i < 4; ++i)
        #pragma unroll
        for (int j = 0; j < 2; ++j)
            #pragma unroll
            for (int k = 0; k < 4; ++k) c[i][j][k] = 0.0f;

    auto load_chunk = [&](int ch) {
        const int buf = ch & (STAGES - 1);
        const uint32_t sa = sbase + buf * STAGE_BYTES;
        const uint32_t sb = sa + A_BYTES;
        const int k0 = ch * BK;
        #pragma unroll
        for (int it = 0; it < 4; ++it) {           // A: 128 rows x 8 granules
            int idx = tid + it * NTHREADS;
            int row = idx >> 3, g = idx & 7;
            CP_ASYNC16(sa + SWZ(row * 128 + g * 16),
                       ag + (size_t)row * H + k0 + g * 8);
        }
        #pragma unroll
        for (int it = 0; it < 2; ++it) {           // B: 64 rows x 8 granules
            int idx = tid + it * NTHREADS;
            int row = idx >> 3, g = idx & 7;
            CP_ASYNC16(sb + SWZ(row * 128 + g * 16),
                       bg + (size_t)row * H + k0 + g * 8);
        }
        CP_COMMIT();
    };

    load_chunk(0);
    load_chunk(1);

    const int g8 = lane >> 3, r8 = lane & 7;

    for (int ch = 0; ch < NCHUNK; ch += 2) {
        CP_WAIT0();          // chunks ch, ch+1 resident
        __syncthreads();     // everyone done reading bufs (ch+2)&3, (ch+3)&3

        if (ch + 2 < NCHUNK) load_chunk(ch + 2);
        if (ch + 3 < NCHUNK) load_chunk(ch + 3);

        // f16 pair accumulators (persist across the 2-chunk pair = K=128)
        uint32_t hc[4][2][2];
        #pragma unroll
        for (int mi = 0; mi < 4; ++mi)
            #pragma unroll
            for (int ni = 0; ni < 2; ++ni)
                hc[mi][ni][0] = hc[mi][ni][1] = 0u;

        #pragma unroll
        for (int half = 0; half < 2; ++half) {     // chunk ch, then ch+1
            const uint32_t sa = sbase + ((ch + half) & (STAGES - 1)) * STAGE_BYTES;
            const uint32_t sb = sa + A_BYTES;

            #pragma unroll
            for (int j = 0; j < 4; ++j) {   // 4 k16 steps per 64-chunk
                uint32_t a[4][4];
                #pragma unroll
                for (int mi = 0; mi < 4; ++mi) {
                    int row = warp_m * 64 + mi * 16 + (g8 & 1) * 8 + r8;
                    int kb = j * 32 + (g8 >> 1) * 16;
                    LDSM4(a[mi][0], a[mi][1], a[mi][2], a[mi][3],
                          sa + SWZ(row * 128 + kb));
                }
                uint32_t b[2][2];
                {
                    int row = warp_n * 16 + (g8 >> 1) * 8 + r8;
                    int kb = j * 32 + (g8 & 1) * 16;
                    LDSM4(b[0][0], b[0][1], b[1][0], b[1][1],
                          sb + SWZ(row * 128 + kb));
                }
                #pragma unroll
                for (int mi = 0; mi < 4; ++mi)
                    #pragma unroll
                    for (int ni = 0; ni < 2; ++ni)
                        MMA16816F16(hc[mi][ni], a[mi], b[ni]);
            }
        }

        // promote f16 pair partials (K=128) into fp32 masters
        #pragma unroll
        for (int mi = 0; mi < 4; ++mi)
            #pragma unroll
            for (int ni = 0; ni < 2; ++ni) {
                float2 lo = __half22float2(*(__half2*)&hc[mi][ni][0]);
                float2 hi = __half22float2(*(__half2*)&hc[mi][ni][1]);
                c[mi][ni][0] += lo.x;
                c[mi][ni][1] += lo.y;
                c[mi][ni][2] += hi.x;
                c[mi][ni][3] += hi.y;
            }
    }

    // ---- fused epilogue: Sum(exp(logit)) per row + target-logit gather ----
    const int tgrp = lane >> 2;   // row-in-8
    const int tcol = lane & 3;    // col pair index

    #pragma unroll
    for (int mi = 0; mi < 4; ++mi) {
        const int row0 = m_base + warp_m * 64 + mi * 16 + tgrp;
        const int row1 = row0 + 8;
        const int t0 = (int)y[row0] - (v_base + warp_n * 16);  // target col in warp tile
        const int t1 = (int)y[row1] - (v_base + warp_n * 16);

        float s0 = 0.0f, s1 = 0.0f;
        #pragma unroll
        for (int ni = 0; ni < 2; ++ni) {
            s0 += __expf(c[mi][ni][0]) + __expf(c[mi][ni][1]);
            s1 += __expf(c[mi][ni][2]) + __expf(c[mi][ni][3]);
        }
        if (t0 >= 0 && t0 < 16 && ((t0 & 7) >> 1) == tcol)
            g_tok[z * M + row0] = c[mi][t0 >> 3][t0 & 1];
        if (t1 >= 0 && t1 < 16 && ((t1 & 7) >> 1) == tcol)
            g_tok[z * M + row1] = c[mi][t1 >> 3][2 + (t1 & 1)];

        s0 += __shfl_xor_sync(0xFFFFFFFFu, s0, 1);
        s0 += __shfl_xor_sync(0xFFFFFFFFu, s0, 2);
        s1 += __shfl_xor_sync(0xFFFFFFFFu, s1, 1);
        s1 += __shfl_xor_sync(0xFFFFFFFFu, s1, 2);
        if (tcol == 0) {
            atomicAdd(&s_row[warp_m * 64 + mi * 16 + tgrp], s0);
            atomicAdd(&s_row[warp_m * 64 + mi * 16 + tgrp + 8], s1);
        }
    }
    __syncthreads();
    if (tid < BM) atomicAdd(&g_sumexp[z * M + m_base + tid], s_row[tid]);
}

// ===================== parallel per-token logp reduction =====================
__global__ void logp_kernel(const long long* __restrict__ y) {
    __shared__ float s_sum[16];
    __shared__ int s_cnt[8];
    if (threadIdx.x < 16) s_sum[threadIdx.x] = 0.0f;
    if (threadIdx.x < 8) s_cnt[threadIdx.x] = 0;
    __syncthreads();

    const int t = blockIdx.x * blockDim.x + threadIdx.x;  // 4096 threads = M tokens
    if (t < M) {
        long long yt = y[t];
        if (yt != -100) {
            int seq = t >> 9;  // 512 tokens per sequence
            float p0 = g_tok[t]     - __logf(g_sumexp[t]);
            float p1 = g_tok[M + t] - __logf(g_sumexp[M + t]);
            atomicAdd(&s_sum[seq], p0);
            atomicAdd(&s_sum[8 + seq], p1);
            atomicAdd(&s_cnt[seq], 1);
        }
    }
    __syncthreads();
    if (threadIdx.x < 16 && s_sum[threadIdx.x] != 0.0f)
        atomicAdd(&g_seqsum[threadIdx.x], s_sum[threadIdx.x]);
    if (threadIdx.x < 8 && s_cnt[threadIdx.x] != 0)
        atomicAdd(&g_seqcnt[threadIdx.x], s_cnt[threadIdx.x]);
}

// ===================== DPO combine (tiny) =====================
__global__ void loss_kernel(float* __restrict__ out) {
    if (threadIdx.x == 0) {
        float loss = 0.0f;
        for (int i = 0; i < 4; ++i) {
            int cc = g_seqcnt[i] > 0 ? g_seqcnt[i] : 1;
            int cr = g_seqcnt[4 + i] > 0 ? g_seqcnt[4 + i] : 1;
            float pc = g_seqsum[i] / cc;
            float pr = g_seqsum[4 + i] / cr;
            float rc = g_seqsum[8 + i] / cc;
            float rr = g_seqsum[12 + i] / cr;
            float zd = 0.1f * ((pc - rc) - (pr - rr));
            loss += (zd > 0.0f) ? log1pf(expf(-zd)) : (-zd + log1pf(expf(zd)));
        }
        out[0] = loss * 0.25f;
    }
}

// ===================== launcher =====================
extern "C" void kernel_launch(void* const* d_in, const int* in_sizes, int n_in,
                              void* d_out, int out_size) {
    const float* x     = (const float*)d_in[0];
    const long long* y = (const long long*)d_in[1];
    const float* Wm    = (const float*)d_in[2];
    const float* rWm   = (const float*)d_in[3];
    float* out         = (float*)d_out;

    cudaFuncSetAttribute(dpo_gemm_kernel,
                         cudaFuncAttributeMaxDynamicSharedMemorySize, SMEM_BYTES);

    zero_kernel<<<32, 256>>>();
    cvt_kernel<<<2048, 256>>>((const float4*)x,   (long)M * H / 4, 0);
    cvt_kernel<<<8192, 256>>>((const float4*)Wm,  (long)V * H / 4, 1);
    cvt_kernel<<<8192, 256>>>((const float4*)rWm, (long)V * H / 4, 2);

    dim3 grid(M / BM, V / BN, 2);
    dpo_gemm_kernel<<<grid, NTHREADS, SMEM_BYTES>>>(y);

    logp_kernel<<<16, 256>>>(y);
    loss_kernel<<<1, 32>>>(out);
}

// round 14
// speedup vs baseline: 1.4162x; 1.1330x over previous
#include <cuda_runtime.h>
#include <cuda_fp16.h>
#include <cstdint>

// ===================== problem constants =====================
static constexpr int H = 4096;        // hidden (K)
static constexpr int V = 32000;       // vocab (N)
static constexpr int M = 4096;        // tokens (8*512)
static constexpr int BM = 128;        // CTA M tile
static constexpr int BN = 64;         // CTA N tile (2 CTAs/SM co-resident)
static constexpr int BK = 64;         // K chunk (128B of fp16 per row = SW128 atom)
static constexpr int NCHUNK = H / BK; // 64 (processed in pairs)
static constexpr int STAGES = 4;
static constexpr int NTHREADS = 256;  // 8 warps: 4 (m) x 2 (n), warp tile 32x32
static constexpr int A_BYTES = BM * BK * 2;           // 16 KB
static constexpr int B_BYTES = BN * BK * 2;           // 8 KB
static constexpr int STAGE_BYTES = A_BYTES + B_BYTES; // 24 KB
static constexpr int SMEM_ROWSUM_OFF = STAGES * STAGE_BYTES; // 98304
static constexpr int SMEM_BYTES = SMEM_ROWSUM_OFF + BM * 4;  // 98816 (x2 < 228KB)

// ===================== device scratch =====================
__device__ __align__(16) __half g_xh[M * H];      // 32 MB fp16
__device__ __align__(16) __half g_wh[2][V * H];   // 2 x 262 MB fp16
__device__ float g_sumexp[2 * M];
__device__ float g_tok[2 * M];
__device__ float g_seqsum[16];   // [0..7] policy per-seq, [8..15] ref per-seq
__device__ int   g_seqcnt[8];

// ===================== helpers =====================
#define SWZ(o) ((o) ^ (((o) >> 3) & 0x70))

__device__ __forceinline__ uint32_t smem_to_u32(const void* p) {
    uint32_t a;
    asm("{ .reg .u64 t; cvta.to.shared.u64 t, %1; cvt.u32.u64 %0, t; }" : "=r"(a) : "l"(p));
    return a;
}

#define CP_ASYNC16(dst_u32, src_ptr) \
    asm volatile("cp.async.cg.shared.global [%0], [%1], 16;" \
                 :: "r"(dst_u32), "l"(src_ptr) : "memory")
#define CP_COMMIT() asm volatile("cp.async.commit_group;" ::: "memory")
#define CP_WAIT0()  asm volatile("cp.async.wait_group 0;" ::: "memory")

#define LDSM4(r0, r1, r2, r3, addr) \
    asm volatile("ldmatrix.sync.aligned.m8n8.x4.shared.b16 {%0,%1,%2,%3}, [%4];" \
                 : "=r"(r0), "=r"(r1), "=r"(r2), "=r"(r3) : "r"(addr))

// f16-accumulate HMMA: D(2 regs = 4 halves) = A(4) * B(2) + C(2)
#define MMA16816F16(c, a, b) \
    asm volatile("mma.sync.aligned.m16n8k16.row.col.f16.f16.f16.f16 " \
                 "{%0,%1}, {%2,%3,%4,%5}, {%6,%7}, {%0,%1};" \
                 : "+r"((c)[0]), "+r"((c)[1]) \
                 : "r"((a)[0]), "r"((a)[1]), "r"((a)[2]), "r"((a)[3]), \
                   "r"((b)[0]), "r"((b)[1]))

// ===================== small kernels =====================
__global__ void zero_kernel() {
    int i = blockIdx.x * blockDim.x + threadIdx.x;
    if (i < 2 * M) {
        g_sumexp[i] = 0.0f;
        g_tok[i] = 0.0f;
    }
    if (i < 16) g_seqsum[i] = 0.0f;
    if (i < 8) g_seqcnt[i] = 0;
}

// which: 0 -> g_xh, 1 -> g_wh[0], 2 -> g_wh[1]
__global__ void cvt_kernel(const float4* __restrict__ s, long n4, int which) {
    __half2* d = (which == 0) ? (__half2*)g_xh : (__half2*)g_wh[which - 1];
    long i = blockIdx.x * (long)blockDim.x + threadIdx.x;
    long stride = (long)gridDim.x * blockDim.x;
    for (; i < n4; i += stride) {
        float4 v = s[i];
        d[2 * i]     = __floats2half2_rn(v.x, v.y);
        d[2 * i + 1] = __floats2half2_rn(v.z, v.w);
    }
}

// ===================== main GEMM + fused softmax-stats kernel =====================
// grid (M/BM=32, V/BN=500, 2), block 256 (8 warps: 4 m x 2 n, warp tile 32x32)
// 4m x 2n warp layout minimizes smem re-reads (A x2 + B x4 = 64KB/chunk vs 80KB
// for 2m x 4n). Chunks processed in pairs: one wait+sync+promote per 2 chunks.
__global__ void __launch_bounds__(NTHREADS, 2) dpo_gemm_kernel(
    const long long* __restrict__ y) {
    extern __shared__ char smem[];
    const uint32_t sbase = smem_to_u32(smem);
    const int tid = threadIdx.x;
    const int wid = tid >> 5, lane = tid & 31;
    const int m_base = blockIdx.x * BM;
    const int v_base = blockIdx.y * BN;
    const int z = blockIdx.z;
    const int warp_m = wid & 3;   // 0..3
    const int warp_n = wid >> 2;  // 0..1

    float* s_row = (float*)(smem + SMEM_ROWSUM_OFF);
    if (tid < BM) s_row[tid] = 0.0f;

    const __half* __restrict__ ag = g_xh + (size_t)m_base * H;
    const __half* __restrict__ bg = g_wh[z] + (size_t)v_base * H;

    // fp32 master accumulators: 2 m16 x 4 n8 x 4 = 32 regs
    float c[2][4][4];
    #pragma unroll
    for (int i = 0; i < 2; ++i)
        #pragma unroll
        for (int j = 0; j < 4; ++j)
            #pragma unroll
            for (int k = 0; k < 4; ++k) c[i][j][k] = 0.0f;

    auto load_chunk = [&](int ch) {
        const int buf = ch & (STAGES - 1);
        const uint32_t sa = sbase + buf * STAGE_BYTES;
        const uint32_t sb = sa + A_BYTES;
        const int k0 = ch * BK;
        #pragma unroll
        for (int it = 0; it < 4; ++it) {           // A: 128 rows x 8 granules
            int idx = tid + it * NTHREADS;
            int row = idx >> 3, g = idx & 7;
            CP_ASYNC16(sa + SWZ(row * 128 + g * 16),
                       ag + (size_t)row * H + k0 + g * 8);
        }
        #pragma unroll
        for (int it = 0; it < 2; ++it) {           // B: 64 rows x 8 granules
            int idx = tid + it * NTHREADS;
            int row = idx >> 3, g = idx & 7;
            CP_ASYNC16(sb + SWZ(row * 128 + g * 16),
                       bg + (size_t)row * H + k0 + g * 8);
        }
        CP_COMMIT();
    };

    load_chunk(0);
    load_chunk(1);

    const int g8 = lane >> 3, r8 = lane & 7;

    for (int ch = 0; ch < NCHUNK; ch += 2) {
        CP_WAIT0();          // chunks ch, ch+1 resident
        __syncthreads();     // everyone done reading bufs (ch+2)&3, (ch+3)&3

        if (ch + 2 < NCHUNK) load_chunk(ch + 2);
        if (ch + 3 < NCHUNK) load_chunk(ch + 3);

        // f16 pair accumulators (persist across the 2-chunk pair = K=128)
        uint32_t hc[2][4][2];
        #pragma unroll
        for (int mi = 0; mi < 2; ++mi)
            #pragma unroll
            for (int ni = 0; ni < 4; ++ni)
                hc[mi][ni][0] = hc[mi][ni][1] = 0u;

        #pragma unroll
        for (int half = 0; half < 2; ++half) {     // chunk ch, then ch+1
            const uint32_t sa = sbase + ((ch + half) & (STAGES - 1)) * STAGE_BYTES;
            const uint32_t sb = sa + A_BYTES;

            #pragma unroll
            for (int j = 0; j < 4; ++j) {   // 4 k16 steps per 64-chunk
                uint32_t a[2][4];
                #pragma unroll
                for (int mi = 0; mi < 2; ++mi) {
                    int row = warp_m * 32 + mi * 16 + (g8 & 1) * 8 + r8;
                    int kb = j * 32 + (g8 >> 1) * 16;
                    LDSM4(a[mi][0], a[mi][1], a[mi][2], a[mi][3],
                          sa + SWZ(row * 128 + kb));
                }
                uint32_t b[4][2];
                #pragma unroll
                for (int p = 0; p < 2; ++p) {
                    int row = warp_n * 32 + p * 16 + (g8 >> 1) * 8 + r8;
                    int kb = j * 32 + (g8 & 1) * 16;
                    LDSM4(b[2 * p][0], b[2 * p][1], b[2 * p + 1][0], b[2 * p + 1][1],
                          sb + SWZ(row * 128 + kb));
                }
                #pragma unroll
                for (int mi = 0; mi < 2; ++mi)
                    #pragma unroll
                    for (int ni = 0; ni < 4; ++ni)
                        MMA16816F16(hc[mi][ni], a[mi], b[ni]);
            }
        }

        // promote f16 pair partials (K=128) into fp32 masters
        #pragma unroll
        for (int mi = 0; mi < 2; ++mi)
            #pragma unroll
            for (int ni = 0; ni < 4; ++ni) {
                float2 lo = __half22float2(*(__half2*)&hc[mi][ni][0]);
                float2 hi = __half22float2(*(__half2*)&hc[mi][ni][1]);
                c[mi][ni][0] += lo.x;
                c[mi][ni][1] += lo.y;
                c[mi][ni][2] += hi.x;
                c[mi][ni][3] += hi.y;
            }
    }

    // ---- fused epilogue: Sum(exp(logit)) per row + target-logit gather ----
    const int tgrp = lane >> 2;   // row-in-8
    const int tcol = lane & 3;    // col pair index

    #pragma unroll
    for (int mi = 0; mi < 2; ++mi) {
        const int lrow0 = warp_m * 32 + mi * 16 + tgrp;
        const int row0 = m_base + lrow0;
        const int row1 = row0 + 8;
        const int t0 = (int)y[row0] - (v_base + warp_n * 32);  // target col in warp tile
        const int t1 = (int)y[row1] - (v_base + warp_n * 32);

        float s0 = 0.0f, s1 = 0.0f;
        #pragma unroll
        for (int ni = 0; ni < 4; ++ni) {
            s0 += __expf(c[mi][ni][0]) + __expf(c[mi][ni][1]);
            s1 += __expf(c[mi][ni][2]) + __expf(c[mi][ni][3]);
        }
        if (t0 >= 0 && t0 < 32 && (((t0 & 7) >> 1) == tcol))
            g_tok[z * M + row0] = c[mi][t0 >> 3][t0 & 1];
        if (t1 >= 0 && t1 < 32 && (((t1 & 7) >> 1) == tcol))
            g_tok[z * M + row1] = c[mi][t1 >> 3][2 + (t1 & 1)];

        s0 += __shfl_xor_sync(0xFFFFFFFFu, s0, 1);
        s0 += __shfl_xor_sync(0xFFFFFFFFu, s0, 2);
        s1 += __shfl_xor_sync(0xFFFFFFFFu, s1, 1);
        s1 += __shfl_xor_sync(0xFFFFFFFFu, s1, 2);
        if (tcol == 0) {
            atomicAdd(&s_row[lrow0], s0);
            atomicAdd(&s_row[lrow0 + 8], s1);
        }
    }
    __syncthreads();
    if (tid < BM) atomicAdd(&g_sumexp[z * M + m_base + tid], s_row[tid]);
}

// ===================== parallel per-token logp reduction =====================
__global__ void logp_kernel(const long long* __restrict__ y) {
    __shared__ float s_sum[16];
    __shared__ int s_cnt[8];
    if (threadIdx.x < 16) s_sum[threadIdx.x] = 0.0f;
    if (threadIdx.x < 8) s_cnt[threadIdx.x] = 0;
    __syncthreads();

    const int t = blockIdx.x * blockDim.x + threadIdx.x;  // 4096 threads = M tokens
    if (t < M) {
        long long yt = y[t];
        if (yt != -100) {
            int seq = t >> 9;  // 512 tokens per sequence
            float p0 = g_tok[t]     - __logf(g_sumexp[t]);
            float p1 = g_tok[M + t] - __logf(g_sumexp[M + t]);
            atomicAdd(&s_sum[seq], p0);
            atomicAdd(&s_sum[8 + seq], p1);
            atomicAdd(&s_cnt[seq], 1);
        }
    }
    __syncthreads();
    if (threadIdx.x < 16 && s_sum[threadIdx.x] != 0.0f)
        atomicAdd(&g_seqsum[threadIdx.x], s_sum[threadIdx.x]);
    if (threadIdx.x < 8 && s_cnt[threadIdx.x] != 0)
        atomicAdd(&g_seqcnt[threadIdx.x], s_cnt[threadIdx.x]);
}

// ===================== DPO combine (tiny) =====================
__global__ void loss_kernel(float* __restrict__ out) {
    if (threadIdx.x == 0) {
        float loss = 0.0f;
        for (int i = 0; i < 4; ++i) {
            int cc = g_seqcnt[i] > 0 ? g_seqcnt[i] : 1;
            int cr = g_seqcnt[4 + i] > 0 ? g_seqcnt[4 + i] : 1;
            float pc = g_seqsum[i] / cc;
            float pr = g_seqsum[4 + i] / cr;
            float rc = g_seqsum[8 + i] / cc;
            float rr = g_seqsum[12 + i] / cr;
            float zd = 0.1f * ((pc - rc) - (pr - rr));
            loss += (zd > 0.0f) ? log1pf(expf(-zd)) : (-zd + log1pf(expf(zd)));
        }
        out[0] = loss * 0.25f;
    }
}

// ===================== launcher =====================
extern "C" void kernel_launch(void* const* d_in, const int* in_sizes, int n_in,
                              void* d_out, int out_size) {
    const float* x     = (const float*)d_in[0];
    const long long* y = (const long long*)d_in[1];
    const float* Wm    = (const float*)d_in[2];
    const float* rWm   = (const float*)d_in[3];
    float* out         = (float*)d_out;

    cudaFuncSetAttribute(dpo_gemm_kernel,
                         cudaFuncAttributeMaxDynamicSharedMemorySize, SMEM_BYTES);

    zero_kernel<<<32, 256>>>();
    cvt_kernel<<<2048, 256>>>((const float4*)x,   (long)M * H / 4, 0);
    cvt_kernel<<<8192, 256>>>((const float4*)Wm,  (long)V * H / 4, 1);
    cvt_kernel<<<8192, 256>>>((const float4*)rWm, (long)V * H / 4, 2);

    dim3 grid(M / BM, V / BN, 2);
    dpo_gemm_kernel<<<grid, NTHREADS, SMEM_BYTES>>>(y);

    logp_kernel<<<16, 256>>>(y);
    loss_kernel<<<1, 32>>>(out);
}